// round 2
// baseline (speedup 1.0000x reference)
#include <cuda_runtime.h>

// ---------------------------------------------------------------------------
// 2-layer GCN, norm='both':
//   x  = transpose(h) [N,B,F]
//   s  = out_deg(src)^-1/2 ; d = in_deg(dst)^-1/2
//   L1: A1 = d * segsum_dst((x*s)[src]) ; H1 = relu(A1@W1 + b1)
//   L2: out = d * segsum_dst((H1*s)[src]) @ W2 + b2
// W2 is commuted before the second aggregation (aggregation is linear):
//   Z = (H1*s)@W2 ; out = d * segsum_dst(Z[src]) + b2
// Aggregation is gather-based over a dst-CSR built per launch (no fp atomics).
// ---------------------------------------------------------------------------

#define NN   50000
#define EE   800000
#define BB   4
#define FIN  64
#define FH   64
#define FOUT 32
#define BF   (BB * FH)    // 256 floats per node, layers 0/1
#define BO   (BB * FOUT)  // 128 floats per node, layer 2

// Scratch (static __device__ arrays: allocation-free per harness rules)
__device__ int   g_deg_out[NN];
__device__ int   g_deg_in[NN];
__device__ float g_snorm[NN];
__device__ float g_dnorm[NN];
__device__ int   g_rowptr[NN + 1];
__device__ int   g_cursor[NN];
__device__ int   g_col[EE];
__device__ float g_Xs[NN * BF];   // scaled features; reused as H1*s after gemm1
__device__ float g_A1[NN * BF];   // aggregated layer-1 input
__device__ float g_Z[NN * BO];    // (H1*s)@W2

// ---------------------------------------------------------------------------
__global__ void k_zero() {
    int i = blockIdx.x * blockDim.x + threadIdx.x;
    if (i < NN) { g_deg_out[i] = 0; g_deg_in[i] = 0; }
}

__global__ void k_deg(const int* __restrict__ src, const int* __restrict__ dst) {
    int e = blockIdx.x * blockDim.x + threadIdx.x;
    if (e < EE) {
        atomicAdd(&g_deg_out[src[e]], 1);
        atomicAdd(&g_deg_in[dst[e]], 1);
    }
}

__global__ void k_norm() {
    int i = blockIdx.x * blockDim.x + threadIdx.x;
    if (i < NN) {
        g_snorm[i] = rsqrtf((float)max(g_deg_out[i], 1));
        g_dnorm[i] = rsqrtf((float)max(g_deg_in[i], 1));
    }
}

// Single-block exclusive scan of deg_in -> rowptr (+ cursor copy)
__global__ void k_scan() {
    __shared__ int sh[1024];
    int tid = threadIdx.x;
    int running = 0;
    for (int base = 0; base < NN; base += 1024) {
        int i = base + tid;
        int v = (i < NN) ? g_deg_in[i] : 0;
        sh[tid] = v;
        __syncthreads();
        int x = v;
        #pragma unroll
        for (int off = 1; off < 1024; off <<= 1) {
            int y = (tid >= off) ? sh[tid - off] : 0;
            __syncthreads();
            x += y;
            sh[tid] = x;
            __syncthreads();
        }
        int excl = running + x - v;
        if (i < NN) { g_rowptr[i] = excl; g_cursor[i] = excl; }
        int tot = sh[1023];
        __syncthreads();   // protect sh[1023] read vs next chunk's writes
        running += tot;
    }
    if (tid == 0) g_rowptr[NN] = running;
}

__global__ void k_fill(const int* __restrict__ src, const int* __restrict__ dst) {
    int e = blockIdx.x * blockDim.x + threadIdx.x;
    if (e < EE) {
        int p = atomicAdd(&g_cursor[dst[e]], 1);
        g_col[p] = src[e];
    }
}

// Transpose h [B,N,64] -> Xs [N, B*64] and scale by s_norm
__global__ void k_xs(const float* __restrict__ h) {
    int i = blockIdx.x * blockDim.x + threadIdx.x;
    if (i < NN * BF) {
        int n = i >> 8;
        int r = i & 255;
        int b = r >> 6;
        int f = r & 63;
        g_Xs[i] = h[((size_t)b * NN + n) * 64 + f] * g_snorm[n];
    }
}

// Layer-1 aggregation: block per dst node, 256 threads = one (b,f) each.
// 4 independent accumulators break the FFMA RAW chain (4-cyc dep latency).
__global__ void __launch_bounds__(BF) k_agg1() {
    int n = blockIdx.x;
    int tid = threadIdx.x;
    int s = g_rowptr[n], e = g_rowptr[n + 1];
    float a0 = 0.f, a1 = 0.f, a2 = 0.f, a3 = 0.f;
    int i = s;
    for (; i + 4 <= e; i += 4) {
        int c0 = __ldg(&g_col[i]);
        int c1 = __ldg(&g_col[i + 1]);
        int c2 = __ldg(&g_col[i + 2]);
        int c3 = __ldg(&g_col[i + 3]);
        a0 += __ldg(&g_Xs[c0 * BF + tid]);
        a1 += __ldg(&g_Xs[c1 * BF + tid]);
        a2 += __ldg(&g_Xs[c2 * BF + tid]);
        a3 += __ldg(&g_Xs[c3 * BF + tid]);
    }
    for (; i < e; i++) a0 += __ldg(&g_Xs[__ldg(&g_col[i]) * BF + tid]);
    g_A1[n * BF + tid] = ((a0 + a1) + (a2 + a3)) * g_dnorm[n];
}

// GEMM1 + relu + pre-scale by s_norm. W1 column lives in 64 registers/thread.
// Writes H1*s back into g_Xs (dead after k_agg1).
__global__ void __launch_bounds__(256) k_gemm1(const float* __restrict__ W1,
                                               const float* __restrict__ b1) {
    __shared__ float As[BF];
    int tid = threadIdx.x;
    int b = tid >> 6, j = tid & 63;
    float w[64];
    #pragma unroll
    for (int f = 0; f < 64; f++) w[f] = W1[f * 64 + j];
    float bj = b1[j];
    for (int n = blockIdx.x; n < NN; n += gridDim.x) {
        __syncthreads();
        As[tid] = g_A1[n * BF + tid];
        __syncthreads();
        float a0 = 0.f, a1 = 0.f, a2 = 0.f, a3 = 0.f;
        #pragma unroll
        for (int f = 0; f < 64; f += 4) {
            a0 = fmaf(As[b * 64 + f + 0], w[f + 0], a0);
            a1 = fmaf(As[b * 64 + f + 1], w[f + 1], a1);
            a2 = fmaf(As[b * 64 + f + 2], w[f + 2], a2);
            a3 = fmaf(As[b * 64 + f + 3], w[f + 3], a3);
        }
        float r = fmaxf((a0 + a1) + (a2 + a3) + bj, 0.f) * g_snorm[n];
        g_Xs[n * BF + tid] = r;
    }
}

// GEMM2 (64 -> 32), two nodes per block iteration. W2 column in 64 regs/thread.
__global__ void __launch_bounds__(256) k_gemm2(const float* __restrict__ W2) {
    __shared__ float Hs[2 * BF];
    int tid = threadIdx.x;
    int half = tid >> 7;
    int r = tid & 127;
    int b = r >> 5, j = r & 31;
    float w[64];
    #pragma unroll
    for (int f = 0; f < 64; f++) w[f] = W2[f * 32 + j];
    for (int p = blockIdx.x; p < NN / 2; p += gridDim.x) {
        int n = p * 2 + half;
        __syncthreads();
        Hs[half * BF + r]       = g_Xs[n * BF + r];
        Hs[half * BF + 128 + r] = g_Xs[n * BF + 128 + r];
        __syncthreads();
        float a0 = 0.f, a1 = 0.f, a2 = 0.f, a3 = 0.f;
        const float* hrow = &Hs[half * BF + b * 64];
        #pragma unroll
        for (int f = 0; f < 64; f += 4) {
            a0 = fmaf(hrow[f + 0], w[f + 0], a0);
            a1 = fmaf(hrow[f + 1], w[f + 1], a1);
            a2 = fmaf(hrow[f + 2], w[f + 2], a2);
            a3 = fmaf(hrow[f + 3], w[f + 3], a3);
        }
        g_Z[n * BO + r] = (a0 + a1) + (a2 + a3);
    }
}

// Layer-2 aggregation + bias + transpose back to [B,N,32].
__global__ void __launch_bounds__(BO) k_agg2(const float* __restrict__ b2,
                                             float* __restrict__ out) {
    int n = blockIdx.x;
    int tid = threadIdx.x;
    int s = g_rowptr[n], e = g_rowptr[n + 1];
    float a0 = 0.f, a1 = 0.f, a2 = 0.f, a3 = 0.f;
    int i = s;
    for (; i + 4 <= e; i += 4) {
        int c0 = __ldg(&g_col[i]);
        int c1 = __ldg(&g_col[i + 1]);
        int c2 = __ldg(&g_col[i + 2]);
        int c3 = __ldg(&g_col[i + 3]);
        a0 += __ldg(&g_Z[c0 * BO + tid]);
        a1 += __ldg(&g_Z[c1 * BO + tid]);
        a2 += __ldg(&g_Z[c2 * BO + tid]);
        a3 += __ldg(&g_Z[c3 * BO + tid]);
    }
    for (; i < e; i++) a0 += __ldg(&g_Z[__ldg(&g_col[i]) * BO + tid]);
    int b = tid >> 5, j = tid & 31;
    out[((size_t)b * NN + n) * FOUT + j] = ((a0 + a1) + (a2 + a3)) * g_dnorm[n] + b2[j];
}

// ---------------------------------------------------------------------------
extern "C" void kernel_launch(void* const* d_in, const int* in_sizes, int n_in,
                              void* d_out, int out_size) {
    const float* h   = (const float*)d_in[0];
    const float* W1  = (const float*)d_in[1];
    const float* b1  = (const float*)d_in[2];
    const float* W2  = (const float*)d_in[3];
    const float* b2  = (const float*)d_in[4];
    const int*   src = (const int*)d_in[5];
    const int*   dst = (const int*)d_in[6];
    float* out = (float*)d_out;

    k_zero<<<(NN + 255) / 256, 256>>>();
    k_deg <<<(EE + 255) / 256, 256>>>(src, dst);
    k_norm<<<(NN + 255) / 256, 256>>>();
    k_scan<<<1, 1024>>>();
    k_fill<<<(EE + 255) / 256, 256>>>(src, dst);
    k_xs  <<<(NN * BF + 255) / 256, 256>>>(h);
    k_agg1<<<NN, BF>>>();
    k_gemm1<<<592, 256>>>(W1, b1);
    k_gemm2<<<592, 256>>>(W2);
    k_agg2<<<NN, BO>>>(b2, out);
}

// round 3
// speedup vs baseline: 1.1734x; 1.1734x over previous
#include <cuda_runtime.h>

// ---------------------------------------------------------------------------
// 2-layer GCN, norm='both':
//   x  = transpose(h) [N,B,F]
//   s  = out_deg(src)^-1/2 ; d = in_deg(dst)^-1/2
//   L1: A1 = d * segsum_dst((x*s)[src]) ; H1 = relu(A1@W1 + b1)
//   L2: out = d * segsum_dst((H1*s)[src]) @ W2 + b2
// W2 is commuted before the second aggregation (aggregation is linear):
//   Z = (H1*s)@W2 ; out = d * segsum_dst(Z[src]) + b2
// Aggregation is gather-based over a dst-CSR whose per-node ranges are
// allocated by warp-aggregated atomics (UNORDERED offsets — disjointness is
// all the gather needs; no prefix scan anywhere).
// ---------------------------------------------------------------------------

#define NN   50000
#define EE   800000
#define BB   4
#define FIN  64
#define FH   64
#define FOUT 32
#define BF   (BB * FH)    // 256 floats per node, layers 0/1
#define BO   (BB * FOUT)  // 128 floats per node, layer 2

// Scratch (static __device__ arrays: allocation-free per harness rules)
__device__ int   g_deg_out[NN];
__device__ int   g_deg_in[NN];
__device__ float g_snorm[NN];
__device__ float g_dnorm[NN];
__device__ int   g_start[NN];     // unordered CSR range start per dst node
__device__ int   g_cursor[NN];
__device__ int   g_total;
__device__ int   g_col[EE];
__device__ float g_Xs[NN * BF];   // scaled features; reused as H1*s after gemm1
__device__ float g_A1[NN * BF];   // aggregated layer-1 input
__device__ float g_Z[NN * BO];    // (H1*s)@W2

// ---------------------------------------------------------------------------
__global__ void k_zero() {
    int i = blockIdx.x * blockDim.x + threadIdx.x;
    if (i < NN) { g_deg_out[i] = 0; g_deg_in[i] = 0; }
    if (i == 0) g_total = 0;
}

__global__ void k_deg(const int* __restrict__ src, const int* __restrict__ dst) {
    int e = blockIdx.x * blockDim.x + threadIdx.x;
    if (e < EE) {
        atomicAdd(&g_deg_out[src[e]], 1);
        atomicAdd(&g_deg_in[dst[e]], 1);
    }
}

// Norms + warp-aggregated CSR range allocation (NO prefix scan).
__global__ void k_alloc() {
    int i = blockIdx.x * blockDim.x + threadIdx.x;
    int lane = threadIdx.x & 31;
    int deg = 0;
    if (i < NN) {
        int dout = g_deg_out[i];
        deg = g_deg_in[i];
        g_snorm[i] = rsqrtf((float)max(dout, 1));
        g_dnorm[i] = rsqrtf((float)max(deg, 1));
    }
    // warp inclusive scan of deg
    int x = deg;
    #pragma unroll
    for (int off = 1; off < 32; off <<= 1) {
        int y = __shfl_up_sync(0xFFFFFFFF, x, off);
        if (lane >= off) x += y;
    }
    int warpsum = __shfl_sync(0xFFFFFFFF, x, 31);
    int base = 0;
    if (lane == 31) base = atomicAdd(&g_total, warpsum);
    base = __shfl_sync(0xFFFFFFFF, base, 31);
    int excl = base + x - deg;
    if (i < NN) { g_start[i] = excl; g_cursor[i] = excl; }
}

__global__ void k_fill(const int* __restrict__ src, const int* __restrict__ dst) {
    int e = blockIdx.x * blockDim.x + threadIdx.x;
    if (e < EE) {
        int p = atomicAdd(&g_cursor[dst[e]], 1);
        g_col[p] = src[e];
    }
}

// Transpose h [B,N,64] -> Xs [N, B*64] and scale by s_norm
__global__ void k_xs(const float* __restrict__ h) {
    int i = blockIdx.x * blockDim.x + threadIdx.x;
    if (i < NN * BF) {
        int n = i >> 8;
        int r = i & 255;
        int b = r >> 6;
        int f = r & 63;
        g_Xs[i] = h[((size_t)b * NN + n) * 64 + f] * g_snorm[n];
    }
}

// Layer-1 aggregation: block per dst node, 256 threads = one (b,f) each.
// 8-wide independent loads per iteration for MLP against ~250-cyc L2 latency.
__global__ void __launch_bounds__(BF) k_agg1() {
    int n = blockIdx.x;
    int tid = threadIdx.x;
    int s = g_start[n];
    int e = s + g_deg_in[n];
    float a0 = 0.f, a1 = 0.f, a2 = 0.f, a3 = 0.f;
    float a4 = 0.f, a5 = 0.f, a6 = 0.f, a7 = 0.f;
    int i = s;
    for (; i + 8 <= e; i += 8) {
        int c0 = __ldg(&g_col[i]);
        int c1 = __ldg(&g_col[i + 1]);
        int c2 = __ldg(&g_col[i + 2]);
        int c3 = __ldg(&g_col[i + 3]);
        int c4 = __ldg(&g_col[i + 4]);
        int c5 = __ldg(&g_col[i + 5]);
        int c6 = __ldg(&g_col[i + 6]);
        int c7 = __ldg(&g_col[i + 7]);
        a0 += __ldg(&g_Xs[c0 * BF + tid]);
        a1 += __ldg(&g_Xs[c1 * BF + tid]);
        a2 += __ldg(&g_Xs[c2 * BF + tid]);
        a3 += __ldg(&g_Xs[c3 * BF + tid]);
        a4 += __ldg(&g_Xs[c4 * BF + tid]);
        a5 += __ldg(&g_Xs[c5 * BF + tid]);
        a6 += __ldg(&g_Xs[c6 * BF + tid]);
        a7 += __ldg(&g_Xs[c7 * BF + tid]);
    }
    for (; i + 4 <= e; i += 4) {
        int c0 = __ldg(&g_col[i]);
        int c1 = __ldg(&g_col[i + 1]);
        int c2 = __ldg(&g_col[i + 2]);
        int c3 = __ldg(&g_col[i + 3]);
        a0 += __ldg(&g_Xs[c0 * BF + tid]);
        a1 += __ldg(&g_Xs[c1 * BF + tid]);
        a2 += __ldg(&g_Xs[c2 * BF + tid]);
        a3 += __ldg(&g_Xs[c3 * BF + tid]);
    }
    for (; i < e; i++) a0 += __ldg(&g_Xs[__ldg(&g_col[i]) * BF + tid]);
    float r = (((a0 + a1) + (a2 + a3)) + ((a4 + a5) + (a6 + a7))) * g_dnorm[n];
    g_A1[n * BF + tid] = r;
}

// GEMM1 + relu + pre-scale by s_norm. W1 column lives in 64 registers/thread.
// Writes H1*s back into g_Xs (dead after k_agg1).
__global__ void __launch_bounds__(256) k_gemm1(const float* __restrict__ W1,
                                               const float* __restrict__ b1) {
    __shared__ float As[BF];
    int tid = threadIdx.x;
    int b = tid >> 6, j = tid & 63;
    float w[64];
    #pragma unroll
    for (int f = 0; f < 64; f++) w[f] = W1[f * 64 + j];
    float bj = b1[j];
    for (int n = blockIdx.x; n < NN; n += gridDim.x) {
        __syncthreads();
        As[tid] = g_A1[n * BF + tid];
        __syncthreads();
        float a0 = 0.f, a1 = 0.f, a2 = 0.f, a3 = 0.f;
        #pragma unroll
        for (int f = 0; f < 64; f += 4) {
            a0 = fmaf(As[b * 64 + f + 0], w[f + 0], a0);
            a1 = fmaf(As[b * 64 + f + 1], w[f + 1], a1);
            a2 = fmaf(As[b * 64 + f + 2], w[f + 2], a2);
            a3 = fmaf(As[b * 64 + f + 3], w[f + 3], a3);
        }
        float r = fmaxf((a0 + a1) + (a2 + a3) + bj, 0.f) * g_snorm[n];
        g_Xs[n * BF + tid] = r;
    }
}

// GEMM2 (64 -> 32), two nodes per block iteration. W2 column in 64 regs/thread.
__global__ void __launch_bounds__(256) k_gemm2(const float* __restrict__ W2) {
    __shared__ float Hs[2 * BF];
    int tid = threadIdx.x;
    int half = tid >> 7;
    int r = tid & 127;
    int b = r >> 5, j = r & 31;
    float w[64];
    #pragma unroll
    for (int f = 0; f < 64; f++) w[f] = W2[f * 32 + j];
    for (int p = blockIdx.x; p < NN / 2; p += gridDim.x) {
        int n = p * 2 + half;
        __syncthreads();
        Hs[half * BF + r]       = g_Xs[n * BF + r];
        Hs[half * BF + 128 + r] = g_Xs[n * BF + 128 + r];
        __syncthreads();
        float a0 = 0.f, a1 = 0.f, a2 = 0.f, a3 = 0.f;
        const float* hrow = &Hs[half * BF + b * 64];
        #pragma unroll
        for (int f = 0; f < 64; f += 4) {
            a0 = fmaf(hrow[f + 0], w[f + 0], a0);
            a1 = fmaf(hrow[f + 1], w[f + 1], a1);
            a2 = fmaf(hrow[f + 2], w[f + 2], a2);
            a3 = fmaf(hrow[f + 3], w[f + 3], a3);
        }
        g_Z[n * BO + r] = (a0 + a1) + (a2 + a3);
    }
}

// Layer-2 aggregation + bias + transpose back to [B,N,32].
__global__ void __launch_bounds__(BO) k_agg2(const float* __restrict__ b2,
                                             float* __restrict__ out) {
    int n = blockIdx.x;
    int tid = threadIdx.x;
    int s = g_start[n];
    int e = s + g_deg_in[n];
    float a0 = 0.f, a1 = 0.f, a2 = 0.f, a3 = 0.f;
    float a4 = 0.f, a5 = 0.f, a6 = 0.f, a7 = 0.f;
    int i = s;
    for (; i + 8 <= e; i += 8) {
        int c0 = __ldg(&g_col[i]);
        int c1 = __ldg(&g_col[i + 1]);
        int c2 = __ldg(&g_col[i + 2]);
        int c3 = __ldg(&g_col[i + 3]);
        int c4 = __ldg(&g_col[i + 4]);
        int c5 = __ldg(&g_col[i + 5]);
        int c6 = __ldg(&g_col[i + 6]);
        int c7 = __ldg(&g_col[i + 7]);
        a0 += __ldg(&g_Z[c0 * BO + tid]);
        a1 += __ldg(&g_Z[c1 * BO + tid]);
        a2 += __ldg(&g_Z[c2 * BO + tid]);
        a3 += __ldg(&g_Z[c3 * BO + tid]);
        a4 += __ldg(&g_Z[c4 * BO + tid]);
        a5 += __ldg(&g_Z[c5 * BO + tid]);
        a6 += __ldg(&g_Z[c6 * BO + tid]);
        a7 += __ldg(&g_Z[c7 * BO + tid]);
    }
    for (; i < e; i++) a0 += __ldg(&g_Z[__ldg(&g_col[i]) * BO + tid]);
    float acc = ((a0 + a1) + (a2 + a3)) + ((a4 + a5) + (a6 + a7));
    int b = tid >> 5, j = tid & 31;
    out[((size_t)b * NN + n) * FOUT + j] = acc * g_dnorm[n] + b2[j];
}

// ---------------------------------------------------------------------------
extern "C" void kernel_launch(void* const* d_in, const int* in_sizes, int n_in,
                              void* d_out, int out_size) {
    const float* h   = (const float*)d_in[0];
    const float* W1  = (const float*)d_in[1];
    const float* b1  = (const float*)d_in[2];
    const float* W2  = (const float*)d_in[3];
    const float* b2  = (const float*)d_in[4];
    const int*   src = (const int*)d_in[5];
    const int*   dst = (const int*)d_in[6];
    float* out = (float*)d_out;

    k_zero <<<(NN + 255) / 256, 256>>>();
    k_deg  <<<(EE + 255) / 256, 256>>>(src, dst);
    k_alloc<<<(NN + 255) / 256, 256>>>();
    k_fill <<<(EE + 255) / 256, 256>>>(src, dst);
    k_xs   <<<(NN * BF + 255) / 256, 256>>>(h);
    k_agg1 <<<NN, BF>>>();
    k_gemm1<<<592, 256>>>(W1, b1);
    k_gemm2<<<592, 256>>>(W2);
    k_agg2 <<<NN, BO>>>(b2, out);
}

// round 4
// speedup vs baseline: 1.6338x; 1.3924x over previous
#include <cuda_runtime.h>

// ---------------------------------------------------------------------------
// 2-layer GCN, norm='both':
//   s = out_deg^-1/2 ; d = in_deg^-1/2
//   L1: A1 = d * segsum_dst((x*s)[src]) ; H1s = relu(A1@W1 + b1) * s
//   L2: out = d * segsum_dst((H1s@W2)[src]) + b2      (W2 commuted: linearity)
// Gather-based aggregation over unordered per-node CSR ranges (warp-aggregated
// atomic allocation, no scan). Layer-1 gathers read h DIRECTLY (transpose +
// snorm folded into the gather). float4 gathers; f32x2 packed FMA in GEMMs.
// ---------------------------------------------------------------------------

#define NN   50000
#define EE   800000
#define BB   4
#define FH   64
#define FOUT 32
#define BF   (BB * FH)    // 256 floats per node (layer 0/1 rows)
#define BO   (BB * FOUT)  // 128 floats per node (layer 2 rows)

__device__ int   g_deg_out[NN];
__device__ int   g_deg_in[NN];
__device__ float g_snorm[NN];
__device__ float g_dnorm[NN];
__device__ int   g_start[NN];
__device__ int   g_cursor[NN];
__device__ int   g_total;
__device__ int   g_col[EE];
__device__ float g_A1[NN * BF];   // aggregated layer-1 input
__device__ float g_Hs[NN * BF];   // relu(A1@W1+b1)*snorm
__device__ float g_Z[NN * BO];    // Hs@W2

// packed fp32x2 fma (sm_100+): acc = a*b + acc, lanewise on a 64-bit pair
__device__ __forceinline__ void ffma2(float2& acc, float2 a, float2 b) {
    unsigned long long ua = *(unsigned long long*)&a;
    unsigned long long ub = *(unsigned long long*)&b;
    unsigned long long uc = *(unsigned long long*)&acc;
    asm("fma.rn.f32x2 %0, %1, %2, %3;" : "=l"(uc) : "l"(ua), "l"(ub), "l"(uc));
    acc = *(float2*)&uc;
}

// ---------------------------------------------------------------------------
__global__ void k_zero() {
    int i = blockIdx.x * blockDim.x + threadIdx.x;
    if (i < NN) { g_deg_out[i] = 0; g_deg_in[i] = 0; }
    if (i == 0) g_total = 0;
}

__global__ void k_deg(const int* __restrict__ src, const int* __restrict__ dst) {
    int e = blockIdx.x * blockDim.x + threadIdx.x;
    if (e < EE) {
        atomicAdd(&g_deg_out[src[e]], 1);
        atomicAdd(&g_deg_in[dst[e]], 1);
    }
}

// Norms + warp-aggregated CSR range allocation (unordered offsets, no scan).
__global__ void k_alloc() {
    int i = blockIdx.x * blockDim.x + threadIdx.x;
    int lane = threadIdx.x & 31;
    int deg = 0;
    if (i < NN) {
        int dout = g_deg_out[i];
        deg = g_deg_in[i];
        g_snorm[i] = rsqrtf((float)max(dout, 1));
        g_dnorm[i] = rsqrtf((float)max(deg, 1));
    }
    int x = deg;
    #pragma unroll
    for (int off = 1; off < 32; off <<= 1) {
        int y = __shfl_up_sync(0xFFFFFFFF, x, off);
        if (lane >= off) x += y;
    }
    int warpsum = __shfl_sync(0xFFFFFFFF, x, 31);
    int base = 0;
    if (lane == 31) base = atomicAdd(&g_total, warpsum);
    base = __shfl_sync(0xFFFFFFFF, base, 31);
    int excl = base + x - deg;
    if (i < NN) { g_start[i] = excl; g_cursor[i] = excl; }
}

__global__ void k_fill(const int* __restrict__ src, const int* __restrict__ dst) {
    int e = blockIdx.x * blockDim.x + threadIdx.x;
    if (e < EE) {
        int p = atomicAdd(&g_cursor[dst[e]], 1);
        g_col[p] = src[e];
    }
}

// Layer-1 aggregation. 64 threads per node (4 nodes/block); each thread owns
// one float4 of the node's [B*F]=256-float row. Gathers straight from h
// ([B,N,64]) with snorm applied on the fly: transpose+scale folded in.
__global__ void __launch_bounds__(256) k_agg1(const float* __restrict__ h) {
    const float4* __restrict__ h4 = (const float4*)h;
    int tid = threadIdx.x;
    int n = blockIdx.x * 4 + (tid >> 6);
    int t = tid & 63;
    int b = t >> 4;          // batch
    int f4 = t & 15;         // float4 index within feature row
    int rowbase = b * NN;    // h4 row index base: (b*NN + c)*16 + f4
    int s = g_start[n];
    int e = s + g_deg_in[n];
    float4 acc = make_float4(0.f, 0.f, 0.f, 0.f);
    int i = s;
    for (; i + 4 <= e; i += 4) {
        int c0 = __ldg(&g_col[i]);
        int c1 = __ldg(&g_col[i + 1]);
        int c2 = __ldg(&g_col[i + 2]);
        int c3 = __ldg(&g_col[i + 3]);
        float s0 = __ldg(&g_snorm[c0]);
        float s1 = __ldg(&g_snorm[c1]);
        float s2 = __ldg(&g_snorm[c2]);
        float s3 = __ldg(&g_snorm[c3]);
        float4 v0 = __ldg(&h4[(rowbase + c0) * 16 + f4]);
        float4 v1 = __ldg(&h4[(rowbase + c1) * 16 + f4]);
        float4 v2 = __ldg(&h4[(rowbase + c2) * 16 + f4]);
        float4 v3 = __ldg(&h4[(rowbase + c3) * 16 + f4]);
        acc.x = fmaf(v0.x, s0, acc.x); acc.y = fmaf(v0.y, s0, acc.y);
        acc.z = fmaf(v0.z, s0, acc.z); acc.w = fmaf(v0.w, s0, acc.w);
        acc.x = fmaf(v1.x, s1, acc.x); acc.y = fmaf(v1.y, s1, acc.y);
        acc.z = fmaf(v1.z, s1, acc.z); acc.w = fmaf(v1.w, s1, acc.w);
        acc.x = fmaf(v2.x, s2, acc.x); acc.y = fmaf(v2.y, s2, acc.y);
        acc.z = fmaf(v2.z, s2, acc.z); acc.w = fmaf(v2.w, s2, acc.w);
        acc.x = fmaf(v3.x, s3, acc.x); acc.y = fmaf(v3.y, s3, acc.y);
        acc.z = fmaf(v3.z, s3, acc.z); acc.w = fmaf(v3.w, s3, acc.w);
    }
    for (; i < e; i++) {
        int c = __ldg(&g_col[i]);
        float sn = __ldg(&g_snorm[c]);
        float4 v = __ldg(&h4[(rowbase + c) * 16 + f4]);
        acc.x = fmaf(v.x, sn, acc.x); acc.y = fmaf(v.y, sn, acc.y);
        acc.z = fmaf(v.z, sn, acc.z); acc.w = fmaf(v.w, sn, acc.w);
    }
    float dn = g_dnorm[n];
    acc.x *= dn; acc.y *= dn; acc.z *= dn; acc.w *= dn;
    ((float4*)g_A1)[n * 64 + t] = acc;
}

// GEMM1 (64->64) + bias + relu + snorm prescale. f32x2 packed FMA: a-pairs
// from smem (LDS.64), w-pairs in 64 registers. One node per block iteration.
__global__ void __launch_bounds__(256) k_gemm1(const float* __restrict__ W1,
                                               const float* __restrict__ b1) {
    __shared__ float As[BF];
    int tid = threadIdx.x;
    int b = tid >> 6, j = tid & 63;
    float2 w2[32];
    #pragma unroll
    for (int k = 0; k < 32; k++)
        w2[k] = make_float2(W1[(2 * k) * 64 + j], W1[(2 * k + 1) * 64 + j]);
    float bj = b1[j];
    for (int n = blockIdx.x; n < NN; n += gridDim.x) {
        __syncthreads();
        As[tid] = g_A1[n * BF + tid];
        __syncthreads();
        const float2* a2 = (const float2*)&As[b * 64];
        float2 acc = make_float2(0.f, 0.f);
        #pragma unroll
        for (int k = 0; k < 32; k++) ffma2(acc, a2[k], w2[k]);
        float r = fmaxf(acc.x + acc.y + bj, 0.f) * g_snorm[n];
        g_Hs[n * BF + tid] = r;
    }
}

// GEMM2 (64->32), two nodes per block iteration, f32x2 packed FMA.
__global__ void __launch_bounds__(256) k_gemm2(const float* __restrict__ W2) {
    __shared__ float Hs[2][BF];
    int tid = threadIdx.x;
    int half = tid >> 7;
    int r = tid & 127;
    int b = r >> 5, j = r & 31;
    float2 w2[32];
    #pragma unroll
    for (int k = 0; k < 32; k++)
        w2[k] = make_float2(W2[(2 * k) * 32 + j], W2[(2 * k + 1) * 32 + j]);
    for (int p = blockIdx.x; p < NN / 2; p += gridDim.x) {
        int n = p * 2 + half;
        __syncthreads();
        Hs[half][r]       = g_Hs[n * BF + r];
        Hs[half][128 + r] = g_Hs[n * BF + 128 + r];
        __syncthreads();
        const float2* a2 = (const float2*)&Hs[half][b * 64];
        float2 acc = make_float2(0.f, 0.f);
        #pragma unroll
        for (int k = 0; k < 32; k++) ffma2(acc, a2[k], w2[k]);
        g_Z[n * BO + r] = acc.x + acc.y;
    }
}

// Layer-2 aggregation: one warp per node, thread = one float4 of the 128-float
// row. Writes output [B,N,32] with bias.
__global__ void __launch_bounds__(256) k_agg2(const float* __restrict__ b2,
                                              float* __restrict__ out) {
    const float4* __restrict__ Z4 = (const float4*)g_Z;
    int tid = threadIdx.x;
    int n = blockIdx.x * 8 + (tid >> 5);
    int t = tid & 31;
    int b = t >> 3;          // batch
    int f4 = t & 7;          // float4 index within 32-float output row
    int s = g_start[n];
    int e = s + g_deg_in[n];
    float4 acc = make_float4(0.f, 0.f, 0.f, 0.f);
    int i = s;
    for (; i + 4 <= e; i += 4) {
        int c0 = __ldg(&g_col[i]);
        int c1 = __ldg(&g_col[i + 1]);
        int c2 = __ldg(&g_col[i + 2]);
        int c3 = __ldg(&g_col[i + 3]);
        float4 v0 = __ldg(&Z4[c0 * 32 + b * 8 + f4]);
        float4 v1 = __ldg(&Z4[c1 * 32 + b * 8 + f4]);
        float4 v2 = __ldg(&Z4[c2 * 32 + b * 8 + f4]);
        float4 v3 = __ldg(&Z4[c3 * 32 + b * 8 + f4]);
        acc.x += (v0.x + v1.x) + (v2.x + v3.x);
        acc.y += (v0.y + v1.y) + (v2.y + v3.y);
        acc.z += (v0.z + v1.z) + (v2.z + v3.z);
        acc.w += (v0.w + v1.w) + (v2.w + v3.w);
    }
    for (; i < e; i++) {
        int c = __ldg(&g_col[i]);
        float4 v = __ldg(&Z4[c * 32 + b * 8 + f4]);
        acc.x += v.x; acc.y += v.y; acc.z += v.z; acc.w += v.w;
    }
    float dn = g_dnorm[n];
    const float4* b24 = (const float4*)b2;
    float4 bias = __ldg(&b24[f4]);
    float4 o;
    o.x = fmaf(acc.x, dn, bias.x);
    o.y = fmaf(acc.y, dn, bias.y);
    o.z = fmaf(acc.z, dn, bias.z);
    o.w = fmaf(acc.w, dn, bias.w);
    ((float4*)out)[((size_t)b * NN + n) * 8 + f4] = o;
}

// ---------------------------------------------------------------------------
extern "C" void kernel_launch(void* const* d_in, const int* in_sizes, int n_in,
                              void* d_out, int out_size) {
    const float* h   = (const float*)d_in[0];
    const float* W1  = (const float*)d_in[1];
    const float* b1  = (const float*)d_in[2];
    const float* W2  = (const float*)d_in[3];
    const float* b2  = (const float*)d_in[4];
    const int*   src = (const int*)d_in[5];
    const int*   dst = (const int*)d_in[6];
    float* out = (float*)d_out;

    k_zero <<<(NN + 255) / 256, 256>>>();
    k_deg  <<<(EE + 255) / 256, 256>>>(src, dst);
    k_alloc<<<(NN + 255) / 256, 256>>>();
    k_fill <<<(EE + 255) / 256, 256>>>(src, dst);
    k_agg1 <<<NN / 4, 256>>>(h);
    k_gemm1<<<592, 256>>>(W1, b1);
    k_gemm2<<<592, 256>>>(W2);
    k_agg2 <<<NN / 8, 256>>>(b2, out);
}

// round 5
// speedup vs baseline: 1.9381x; 1.1863x over previous
#include <cuda_runtime.h>
#include <cuda_fp16.h>

// ---------------------------------------------------------------------------
// 2-layer GCN, norm='both'. W2 commuted before layer-2 aggregation.
// Gather-based aggregation over unordered CSR ranges (warp-aggregated atomic
// allocation). Gather operands staged in fp16 (halves L2 bytes); fp32 accum.
// agg1+gemm1 fused (persistent blocks, W1 in registers).
// ---------------------------------------------------------------------------

#define NN   50000
#define EE   800000
#define BF   256          // B*FH floats per node row (layers 0/1)
#define BO   128          // B*FOUT floats per node row (layer 2)

__device__ int    g_deg_out[NN];
__device__ int    g_deg_in[NN];
__device__ float  g_snorm[NN];
__device__ float  g_dnorm[NN];
__device__ int    g_start[NN];
__device__ int    g_cursor[NN];
__device__ int    g_total;
__device__ int    g_col[EE];
__device__ uint2  g_Xh[NN * 64];    // fp16 h*snorm, node-major [N][256h] (25.6MB)
__device__ float  g_Hs[NN * BF];    // relu(A1@W1+b1)*snorm (fp32, streamed)
__device__ __half g_Zh[NN * BO];    // Hs@W2 in fp16 (12.8MB, gathered by agg2)

__device__ __forceinline__ void ffma2(float2& acc, float2 a, float2 b) {
    unsigned long long ua = *(unsigned long long*)&a;
    unsigned long long ub = *(unsigned long long*)&b;
    unsigned long long uc = *(unsigned long long*)&acc;
    asm("fma.rn.f32x2 %0, %1, %2, %3;" : "=l"(uc) : "l"(ua), "l"(ub), "l"(uc));
    acc = *(float2*)&uc;
}
__device__ __forceinline__ void acc_u2(float2& a0, float2& a1, uint2 v) {
    a0.x += __low2float(*(__half2*)&v.x);  a0.y += __high2float(*(__half2*)&v.x);
    a1.x += __low2float(*(__half2*)&v.y);  a1.y += __high2float(*(__half2*)&v.y);
}

// ---------------------------------------------------------------------------
__global__ void k_zero() {
    int i = blockIdx.x * blockDim.x + threadIdx.x;
    if (i < NN) { g_deg_out[i] = 0; g_deg_in[i] = 0; }
    if (i == 0) g_total = 0;
}

__global__ void k_deg(const int* __restrict__ src, const int* __restrict__ dst) {
    int e = blockIdx.x * blockDim.x + threadIdx.x;
    if (e < EE) {
        atomicAdd(&g_deg_out[src[e]], 1);
        atomicAdd(&g_deg_in[dst[e]], 1);
    }
}

__global__ void k_alloc() {
    int i = blockIdx.x * blockDim.x + threadIdx.x;
    int lane = threadIdx.x & 31;
    int deg = 0;
    if (i < NN) {
        int dout = g_deg_out[i];
        deg = g_deg_in[i];
        g_snorm[i] = rsqrtf((float)max(dout, 1));
        g_dnorm[i] = rsqrtf((float)max(deg, 1));
    }
    int x = deg;
    #pragma unroll
    for (int off = 1; off < 32; off <<= 1) {
        int y = __shfl_up_sync(0xFFFFFFFF, x, off);
        if (lane >= off) x += y;
    }
    int warpsum = __shfl_sync(0xFFFFFFFF, x, 31);
    int base = 0;
    if (lane == 31) base = atomicAdd(&g_total, warpsum);
    base = __shfl_sync(0xFFFFFFFF, base, 31);
    int excl = base + x - deg;
    if (i < NN) { g_start[i] = excl; g_cursor[i] = excl; }
}

__global__ void k_fill(const int* __restrict__ src, const int* __restrict__ dst) {
    int e = blockIdx.x * blockDim.x + threadIdx.x;
    if (e < EE) {
        int p = atomicAdd(&g_cursor[dst[e]], 1);
        g_col[p] = src[e];
    }
}

// Stage h [B,N,64] -> g_Xh [N][256] fp16, pre-scaled by snorm (transpose folded).
__global__ void __launch_bounds__(256) k_stage(const float* __restrict__ h) {
    const float4* __restrict__ h4 = (const float4*)h;
    int i = blockIdx.x * 256 + threadIdx.x;   // i < NN*64 (one uint2 = 4 halves)
    int n = i >> 6, t = i & 63;
    float4 v = __ldg(&h4[((size_t)(t >> 4) * NN + n) * 16 + (t & 15)]);
    float sn = g_snorm[n];
    __half2 p0 = __floats2half2_rn(v.x * sn, v.y * sn);
    __half2 p1 = __floats2half2_rn(v.z * sn, v.w * sn);
    uint2 u; u.x = *(unsigned*)&p0; u.y = *(unsigned*)&p1;
    g_Xh[i] = u;
}

// Fused agg1 + gemm1. Persistent blocks; 4 nodes per group; 64 threads/node
// gather fp16 rows (uint2 = 4 halves each) into fp32 smem; then all 256
// threads apply W1 (register f32x2 pairs) + bias + relu + snorm -> g_Hs.
__global__ void __launch_bounds__(256, 2) k_fused(const float* __restrict__ W1,
                                                  const float* __restrict__ b1) {
    __shared__ float4 As[4][64];   // 4 nodes x 256 floats
    int tid = threadIdx.x;
    int b = tid >> 6, j = tid & 63;
    float2 w1[32];
    #pragma unroll
    for (int k = 0; k < 32; k++)
        w1[k] = make_float2(W1[(2 * k) * 64 + j], W1[(2 * k + 1) * 64 + j]);
    float bj = b1[j];
    int slot = tid >> 6;       // node slot 0..3
    int t = tid & 63;          // uint2 index within row
    for (int g = blockIdx.x; g < NN / 4; g += gridDim.x) {
        int n = g * 4 + slot;
        int s = g_start[n];
        int e = s + g_deg_in[n];
        float2 p0 = {0.f, 0.f}, p1 = {0.f, 0.f};
        float2 q0 = {0.f, 0.f}, q1 = {0.f, 0.f};
        int i = s;
        for (; i + 8 <= e; i += 8) {
            int c0 = __ldg(&g_col[i]);     int c1 = __ldg(&g_col[i + 1]);
            int c2 = __ldg(&g_col[i + 2]); int c3 = __ldg(&g_col[i + 3]);
            int c4 = __ldg(&g_col[i + 4]); int c5 = __ldg(&g_col[i + 5]);
            int c6 = __ldg(&g_col[i + 6]); int c7 = __ldg(&g_col[i + 7]);
            uint2 v0 = __ldg(&g_Xh[c0 * 64 + t]);
            uint2 v1 = __ldg(&g_Xh[c1 * 64 + t]);
            uint2 v2 = __ldg(&g_Xh[c2 * 64 + t]);
            uint2 v3 = __ldg(&g_Xh[c3 * 64 + t]);
            uint2 v4 = __ldg(&g_Xh[c4 * 64 + t]);
            uint2 v5 = __ldg(&g_Xh[c5 * 64 + t]);
            uint2 v6 = __ldg(&g_Xh[c6 * 64 + t]);
            uint2 v7 = __ldg(&g_Xh[c7 * 64 + t]);
            acc_u2(p0, p1, v0); acc_u2(q0, q1, v1);
            acc_u2(p0, p1, v2); acc_u2(q0, q1, v3);
            acc_u2(p0, p1, v4); acc_u2(q0, q1, v5);
            acc_u2(p0, p1, v6); acc_u2(q0, q1, v7);
        }
        for (; i < e; i++) {
            uint2 v = __ldg(&g_Xh[__ldg(&g_col[i]) * 64 + t]);
            acc_u2(p0, p1, v);
        }
        float dn = g_dnorm[n];
        float4 a;
        a.x = (p0.x + q0.x) * dn;  a.y = (p0.y + q0.y) * dn;
        a.z = (p1.x + q1.x) * dn;  a.w = (p1.y + q1.y) * dn;
        As[slot][t] = a;
        __syncthreads();
        // gemm1: thread = (b, j); loop the 4 nodes of this group.
        #pragma unroll
        for (int nn = 0; nn < 4; nn++) {
            const float4* arow = &As[nn][b * 16];
            float2 acc = {0.f, 0.f};
            #pragma unroll
            for (int k = 0; k < 16; k++) {
                float4 a4 = arow[k];
                ffma2(acc, make_float2(a4.x, a4.y), w1[2 * k]);
                ffma2(acc, make_float2(a4.z, a4.w), w1[2 * k + 1]);
            }
            int nn_g = g * 4 + nn;
            float r = fmaxf(acc.x + acc.y + bj, 0.f) * g_snorm[nn_g];
            g_Hs[nn_g * BF + tid] = r;
        }
        __syncthreads();   // protect As before next group's gather
    }
}

// GEMM2 (64->32), two nodes per iteration, W2 columns in registers, fp16 out.
__global__ void __launch_bounds__(256) k_gemm2(const float* __restrict__ W2) {
    __shared__ float Hs[2][BF];
    int tid = threadIdx.x;
    int half_ = tid >> 7;
    int r = tid & 127;
    int b = r >> 5, j = r & 31;
    float2 w2[32];
    #pragma unroll
    for (int k = 0; k < 32; k++)
        w2[k] = make_float2(W2[(2 * k) * 32 + j], W2[(2 * k + 1) * 32 + j]);
    for (int p = blockIdx.x; p < NN / 2; p += gridDim.x) {
        int n = p * 2 + half_;
        __syncthreads();
        Hs[half_][r]       = g_Hs[n * BF + r];
        Hs[half_][128 + r] = g_Hs[n * BF + 128 + r];
        __syncthreads();
        const float2* a2 = (const float2*)&Hs[half_][b * 64];
        float2 acc = {0.f, 0.f};
        #pragma unroll
        for (int k = 0; k < 32; k++) ffma2(acc, a2[k], w2[k]);
        g_Zh[n * BO + r] = __float2half(acc.x + acc.y);
    }
}

// Layer-2 aggregation over fp16 Z: warp per node, thread = 4 halves (uint2).
__global__ void __launch_bounds__(256) k_agg2(const float* __restrict__ b2,
                                              float* __restrict__ out) {
    const uint2* __restrict__ Z2 = (const uint2*)g_Zh;
    int tid = threadIdx.x;
    int n = blockIdx.x * 8 + (tid >> 5);
    int t = tid & 31;                 // uint2 index in the 32-uint2 row
    int b = t >> 3;                   // batch
    int j4 = t & 7;                   // float4 index in 32-float output row
    int s = g_start[n];
    int e = s + g_deg_in[n];
    float2 p0 = {0.f, 0.f}, p1 = {0.f, 0.f};
    float2 q0 = {0.f, 0.f}, q1 = {0.f, 0.f};
    int i = s;
    for (; i + 4 <= e; i += 4) {
        int c0 = __ldg(&g_col[i]);     int c1 = __ldg(&g_col[i + 1]);
        int c2 = __ldg(&g_col[i + 2]); int c3 = __ldg(&g_col[i + 3]);
        uint2 v0 = __ldg(&Z2[c0 * 32 + t]);
        uint2 v1 = __ldg(&Z2[c1 * 32 + t]);
        uint2 v2 = __ldg(&Z2[c2 * 32 + t]);
        uint2 v3 = __ldg(&Z2[c3 * 32 + t]);
        acc_u2(p0, p1, v0); acc_u2(q0, q1, v1);
        acc_u2(p0, p1, v2); acc_u2(q0, q1, v3);
    }
    for (; i < e; i++) {
        uint2 v = __ldg(&Z2[__ldg(&g_col[i]) * 32 + t]);
        acc_u2(p0, p1, v);
    }
    float dn = g_dnorm[n];
    const float4* b24 = (const float4*)b2;
    float4 bias = __ldg(&b24[j4]);
    float4 o;
    o.x = fmaf(p0.x + q0.x, dn, bias.x);
    o.y = fmaf(p0.y + q0.y, dn, bias.y);
    o.z = fmaf(p1.x + q1.x, dn, bias.z);
    o.w = fmaf(p1.y + q1.y, dn, bias.w);
    ((float4*)out)[((size_t)b * NN + n) * 8 + j4] = o;
}

// ---------------------------------------------------------------------------
extern "C" void kernel_launch(void* const* d_in, const int* in_sizes, int n_in,
                              void* d_out, int out_size) {
    const float* h   = (const float*)d_in[0];
    const float* W1  = (const float*)d_in[1];
    const float* b1  = (const float*)d_in[2];
    const float* W2  = (const float*)d_in[3];
    const float* b2  = (const float*)d_in[4];
    const int*   src = (const int*)d_in[5];
    const int*   dst = (const int*)d_in[6];
    float* out = (float*)d_out;

    k_zero <<<(NN + 255) / 256, 256>>>();
    k_deg  <<<(EE + 255) / 256, 256>>>(src, dst);
    k_alloc<<<(NN + 255) / 256, 256>>>();
    k_fill <<<(EE + 255) / 256, 256>>>(src, dst);
    k_stage<<<NN * 64 / 256, 256>>>(h);
    k_fused<<<296, 256>>>(W1, b1);
    k_gemm2<<<592, 256>>>(W2);
    k_agg2 <<<NN / 8, 256>>>(b2, out);
}